// round 12
// baseline (speedup 1.0000x reference)
#include <cuda_runtime.h>

#define BGRAPHS 64
#define NPG     1024
#define NTOT    (BGRAPHS * NPG)   // 65536
#define DIM     512
#define DROPN   512               // NPG - ceil(0.5*NPG)
#define PPARTS  16                // partial copies per graph (privatized reduce)
#define ECAP    (64 * 1024 * 32)  // dst16 cache capacity (expected E)

// ---- scratch (device globals: no allocation allowed) ----
__device__ float g_h[NTOT];
__device__ float g_norm[NTOT];
__device__ float g_wb[NTOT];
__device__ int   g_pdeg[PPARTS * NTOT];          // 4 MB partial degree hist
__device__ float g_pagg[PPARTS * NTOT];          // 4 MB partial agg sums
__device__ unsigned short g_dst16[ECAP];         // 4 MB compacted local dst

// ---------------------------------------------------------------------------
// Warp-parallel int64-vs-int32 probe (warp 0 of a CTA): node indices < 2^17,
// so int64 data has all odd 32-bit words zero. 32 concurrent loads, one round
// trip, overlapped across CTAs.
// ---------------------------------------------------------------------------
__device__ __forceinline__ int warp_probe_is64(const void* p, long long nelem) {
    const unsigned* w = (const unsigned*)p;
    int lane = threadIdx.x & 31;
    int i = 1 + 2 * lane;
    unsigned v = ((long long)i < nelem * 2) ? w[i] : 0u;
    unsigned any = __ballot_sync(0xffffffffu, v != 0u);
    return any ? 0 : 1;
}

__device__ __forceinline__ int edge_idx(const void* p, long long e, int is64) {
    if (is64) return (int)((const long long*)p)[e];
    return ((const int*)p)[e];
}

// ---------------------------------------------------------------------------
// Degree partials: PPARTS CTAs per graph, shared int histogram, plain stores.
// Vectorized: 8 edges per thread per iteration. Compacts dst to uint16.
// ---------------------------------------------------------------------------
__global__ void k_deg_part(const void* __restrict__ dst, long long EPG,
                           int EPP, int use16, long long E) {
    __shared__ int sacc[NPG];
    __shared__ int s_is64;
    int g = blockIdx.x >> 4;
    int p = blockIdx.x & (PPARTS - 1);
    if (threadIdx.x < 32) {
        int r = warp_probe_is64(dst, E);
        if (threadIdx.x == 0) s_is64 = r;
    }
    for (int j = threadIdx.x; j < NPG; j += blockDim.x) sacc[j] = 0;
    __syncthreads();

    const int is64 = s_is64;
    long long base = (long long)g * EPG + (long long)p * EPP;
    long long rem = EPG - (long long)p * EPP;
    int cnt = (rem < (long long)EPP) ? (rem > 0 ? (int)rem : 0) : EPP;
    const int BS = 256;
    int t = threadIdx.x;
    int nfull = cnt >> 3;

    for (int gi = t; gi < nfull; gi += BS) {
        long long e0 = base + ((long long)gi << 3);
        int d[8];
        if (is64) {
            const longlong4* q = (const longlong4*)((const long long*)dst + e0);
            longlong4 a = q[0], b = q[1];
            d[0] = (int)a.x & (NPG - 1); d[1] = (int)a.y & (NPG - 1);
            d[2] = (int)a.z & (NPG - 1); d[3] = (int)a.w & (NPG - 1);
            d[4] = (int)b.x & (NPG - 1); d[5] = (int)b.y & (NPG - 1);
            d[6] = (int)b.z & (NPG - 1); d[7] = (int)b.w & (NPG - 1);
        } else {
            const int4* q = (const int4*)((const int*)dst + e0);
            int4 a = q[0], b = q[1];
            d[0] = a.x & (NPG - 1); d[1] = a.y & (NPG - 1);
            d[2] = a.z & (NPG - 1); d[3] = a.w & (NPG - 1);
            d[4] = b.x & (NPG - 1); d[5] = b.y & (NPG - 1);
            d[6] = b.z & (NPG - 1); d[7] = b.w & (NPG - 1);
        }
#pragma unroll
        for (int k = 0; k < 8; k++) atomicAdd(&sacc[d[k]], 1);
        if (use16) {
            uint4 s;
            s.x = (unsigned)d[0] | ((unsigned)d[1] << 16);
            s.y = (unsigned)d[2] | ((unsigned)d[3] << 16);
            s.z = (unsigned)d[4] | ((unsigned)d[5] << 16);
            s.w = (unsigned)d[6] | ((unsigned)d[7] << 16);
            *(uint4*)(g_dst16 + e0) = s;
        }
    }
    for (int e = (nfull << 3) + t; e < cnt; e += BS) {
        int d = edge_idx(dst, base + e, is64) & (NPG - 1);
        atomicAdd(&sacc[d], 1);
        if (use16) g_dst16[base + e] = (unsigned short)d;
    }
    __syncthreads();

    int out = p * NTOT + g * NPG;
    for (int j = threadIdx.x; j < NPG; j += blockDim.x)
        g_pdeg[out + j] = sacc[j];
}

// ---------------------------------------------------------------------------
// Fused h+norm: two rows per warp.
//   norm[row] = (sum of 16 deg partials)^-1/2 (0 if isolated) — lanes 0..15
//   reduce row0's partials, lanes 16..31 row1's, hidden under the feature
//   stream. h[row] = dot(features[row,:], weight) * norm[row].
// Default cache policy on features: primes L2 for k_gate's re-read.
// ---------------------------------------------------------------------------
__global__ void __launch_bounds__(256) k_h(const float* __restrict__ feat,
                                           const float* __restrict__ weight) {
    __shared__ float4 swt[DIM / 4];
    int t = threadIdx.x;
    if (t < DIM / 4) swt[t] = ((const float4*)weight)[t];
    __syncthreads();

    int warp = t >> 5, lane = t & 31;
    int row0 = (blockIdx.x * (blockDim.x >> 5) + warp) * 2;
    if (row0 >= NTOT) return;
    int row1 = row0 + 1;

    // norm from degree partials (16 lanes per row, shfl tree within halves)
    int myrow = (lane < 16) ? row0 : row1;
    int c = g_pdeg[(lane & 15) * NTOT + myrow];
#pragma unroll
    for (int o = 8; o > 0; o >>= 1) c += __shfl_down_sync(0xffffffffu, c, o);
    // lane 0 holds deg(row0), lane 16 holds deg(row1)

    const float4* f0 = (const float4*)(feat + (long long)row0 * DIM);
    const float4* f1 = f0 + DIM / 4;
    float a0 = 0.f, a1 = 0.f;
#pragma unroll
    for (int k = 0; k < 4; k++) {
        float4 x = f0[lane + 32 * k];
        float4 y = f1[lane + 32 * k];
        float4 b = swt[lane + 32 * k];
        a0 += x.x * b.x + x.y * b.y + x.z * b.z + x.w * b.w;
        a1 += y.x * b.x + y.y * b.y + y.z * b.z + y.w * b.w;
    }
#pragma unroll
    for (int o = 16; o > 0; o >>= 1) {
        a0 += __shfl_down_sync(0xffffffffu, a0, o);
        a1 += __shfl_down_sync(0xffffffffu, a1, o);
    }
    // a0, a1 complete at lane 0; send a1 to lane 16
    a1 = __shfl_sync(0xffffffffu, a1, 0);
    if (lane == 0) {
        float nrm = (c > 0) ? rsqrtf((float)c) : 0.f;
        g_norm[row0] = nrm;
        g_h[row0] = a0 * nrm;
    } else if (lane == 16) {
        float nrm = (c > 0) ? rsqrtf((float)c) : 0.f;
        g_norm[row1] = nrm;
        g_h[row1] = a1 * nrm;
    }
}

// ---------------------------------------------------------------------------
// Agg partials: PPARTS CTAs per graph. h staged in shared, shared float
// accumulator, plain stores. Vectorized: 8 edges per thread per iteration.
// ---------------------------------------------------------------------------
__global__ void k_agg_part(const void* __restrict__ src,
                           const void* __restrict__ dst, long long EPG,
                           int EPP, int use16, long long E) {
    __shared__ float sh[NPG];
    __shared__ float sacc[NPG];
    __shared__ int s_is64;
    int g = blockIdx.x >> 4;
    int p = blockIdx.x & (PPARTS - 1);
    int hb = g * NPG;
    if (threadIdx.x < 32) {
        int r = warp_probe_is64(src, E);
        if (threadIdx.x == 0) s_is64 = r;
    }
    for (int j = threadIdx.x; j < NPG; j += blockDim.x) {
        sh[j] = g_h[hb + j];
        sacc[j] = 0.f;
    }
    __syncthreads();

    const int is64 = s_is64;
    long long base = (long long)g * EPG + (long long)p * EPP;
    long long rem = EPG - (long long)p * EPP;
    int cnt = (rem < (long long)EPP) ? (rem > 0 ? (int)rem : 0) : EPP;
    const int BS = 256;
    int t = threadIdx.x;
    int nfull = cnt >> 3;

    for (int gi = t; gi < nfull; gi += BS) {
        long long e0 = base + ((long long)gi << 3);
        int s[8], d[8];
        if (is64) {
            const longlong4* q = (const longlong4*)((const long long*)src + e0);
            longlong4 a = q[0], b = q[1];
            s[0] = (int)a.x & (NPG - 1); s[1] = (int)a.y & (NPG - 1);
            s[2] = (int)a.z & (NPG - 1); s[3] = (int)a.w & (NPG - 1);
            s[4] = (int)b.x & (NPG - 1); s[5] = (int)b.y & (NPG - 1);
            s[6] = (int)b.z & (NPG - 1); s[7] = (int)b.w & (NPG - 1);
        } else {
            const int4* q = (const int4*)((const int*)src + e0);
            int4 a = q[0], b = q[1];
            s[0] = a.x & (NPG - 1); s[1] = a.y & (NPG - 1);
            s[2] = a.z & (NPG - 1); s[3] = a.w & (NPG - 1);
            s[4] = b.x & (NPG - 1); s[5] = b.y & (NPG - 1);
            s[6] = b.z & (NPG - 1); s[7] = b.w & (NPG - 1);
        }
        if (use16) {
            uint4 q = *(const uint4*)(g_dst16 + e0);
            d[0] = (int)(q.x & 0xffffu); d[1] = (int)(q.x >> 16);
            d[2] = (int)(q.y & 0xffffu); d[3] = (int)(q.y >> 16);
            d[4] = (int)(q.z & 0xffffu); d[5] = (int)(q.z >> 16);
            d[6] = (int)(q.w & 0xffffu); d[7] = (int)(q.w >> 16);
        } else if (is64) {
            const longlong4* q = (const longlong4*)((const long long*)dst + e0);
            longlong4 a = q[0], b = q[1];
            d[0] = (int)a.x & (NPG - 1); d[1] = (int)a.y & (NPG - 1);
            d[2] = (int)a.z & (NPG - 1); d[3] = (int)a.w & (NPG - 1);
            d[4] = (int)b.x & (NPG - 1); d[5] = (int)b.y & (NPG - 1);
            d[6] = (int)b.z & (NPG - 1); d[7] = (int)b.w & (NPG - 1);
        } else {
            const int4* q = (const int4*)((const int*)dst + e0);
            int4 a = q[0], b = q[1];
            d[0] = a.x & (NPG - 1); d[1] = a.y & (NPG - 1);
            d[2] = a.z & (NPG - 1); d[3] = a.w & (NPG - 1);
            d[4] = b.x & (NPG - 1); d[5] = b.y & (NPG - 1);
            d[6] = b.z & (NPG - 1); d[7] = b.w & (NPG - 1);
        }
#pragma unroll
        for (int k = 0; k < 8; k++) atomicAdd(&sacc[d[k]], sh[s[k]]);
    }
    for (int e = (nfull << 3) + t; e < cnt; e += BS) {
        int si = edge_idx(src, base + e, is64) & (NPG - 1);
        int di = use16 ? (int)g_dst16[base + e]
                       : (edge_idx(dst, base + e, is64) & (NPG - 1));
        atomicAdd(&sacc[di], sh[si]);
    }
    __syncthreads();

    int out = p * NTOT + g * NPG;
    for (int j = threadIdx.x; j < NPG; j += blockDim.x)
        g_pagg[out + j] = sacc[j];
}

// ---------------------------------------------------------------------------
// Fused w + select-based top-k mask. One 1024-thread CTA per graph.
//   w_i = relu((sum agg partials)*norm + bias)
//   T   = key at stable-sort position DROPN-1 (4-pass MSD radix select)
//   keep iff key>T or (key==T and #{j<i: key_j==T} >= DROPN - #{key<T})
// Identical to rank_i = #{w_j<w_i}+#{j<i: w_j==w_i} >= DROPN.
// ---------------------------------------------------------------------------
__global__ void k_rank(const float* __restrict__ bias) {
    __shared__ int sbin[256];
    __shared__ int s_sel[2];
    __shared__ int s_wsum[32];
    __shared__ int s_nless;

    int g = blockIdx.x;
    int base = g * NPG;
    int i = threadIdx.x;
    int wid = i >> 5, lane = i & 31;

    float s = 0.f;
#pragma unroll
    for (int p = 0; p < PPARTS; p++) s += g_pagg[p * NTOT + base + i];
    float v = s * g_norm[base + i] + bias[0];
    float w = v > 0.f ? v : 0.f;
    unsigned key = __float_as_uint(w);
    if (i == 0) { s_sel[0] = 0; s_sel[1] = DROPN - 1; s_nless = 0; }
    __syncthreads();

#pragma unroll
    for (int pass = 3; pass >= 0; pass--) {
        int shift = pass * 8;
        if (i < 256) sbin[i] = 0;
        __syncthreads();
        unsigned prefix = (unsigned)s_sel[0];
        bool match = (pass == 3) || ((key >> (shift + 8)) == prefix);
        if (match) atomicAdd(&sbin[(key >> shift) & 255], 1);
        __syncthreads();
        if (i < 32) {
            int r = s_sel[1];
            int loc[8], lsum = 0;
#pragma unroll
            for (int t = 0; t < 8; t++) { loc[t] = sbin[i * 8 + t]; lsum += loc[t]; }
            int incl = lsum;
#pragma unroll
            for (int o = 1; o < 32; o <<= 1) {
                int y = __shfl_up_sync(0xffffffffu, incl, o);
                if (lane >= o) incl += y;
            }
            int excl = incl - lsum;
            bool has = (excl <= r) && (r < incl);
            if (has) {
                int rr = r - excl;
                int b = 0;
#pragma unroll
                for (int t = 0; t < 8; t++) {
                    if (rr >= loc[t] && b == t) { rr -= loc[t]; b = t + 1; }
                }
                int binfull = i * 8 + b;
                s_sel[0] = (pass == 3) ? binfull : (int)((prefix << 8) | (unsigned)binfull);
                s_sel[1] = rr;
            }
        }
        __syncthreads();
    }

    unsigned T = (unsigned)s_sel[0];

    unsigned lm = __ballot_sync(0xffffffffu, key < T);
    unsigned em = __ballot_sync(0xffffffffu, key == T);
    if (lane == 0) {
        atomicAdd(&s_nless, __popc(lm));
        s_wsum[wid] = __popc(em);
    }
    __syncthreads();
    if (i < 32) {
        int x = s_wsum[i];
        int incl = x;
#pragma unroll
        for (int o = 1; o < 32; o <<= 1) {
            int y = __shfl_up_sync(0xffffffffu, incl, o);
            if (lane >= o) incl += y;
        }
        s_wsum[i] = incl - x;
    }
    __syncthreads();

    int pos = s_wsum[wid] + __popc(em & ((1u << lane) - 1u));
    int needEq = DROPN - s_nless;
    bool keep = (key > T) || ((key == T) && (pos >= needEq));
    g_wb[base + i] = keep ? w : 0.f;
}

// ---------------------------------------------------------------------------
// out[n,:] = features[n,:] * wb[n].  4 rows per 256-thread CTA, 2 front-
// batched float4 pairs per thread. Default-policy loads (hit L2 primed by
// k_h); streaming stores (write-once output).
// ---------------------------------------------------------------------------
__global__ void __launch_bounds__(256) k_gate(const float* __restrict__ feat,
                                              float* __restrict__ out) {
    int row = blockIdx.x * 4 + (threadIdx.x >> 6);
    int col = threadIdx.x & 63;
    float wv = g_wb[row];
    const float4* fi = (const float4*)(feat + (long long)row * DIM);
    float4* fo = (float4*)(out + (long long)row * DIM);
    if (wv == 0.f) {
        float4 z = make_float4(0.f, 0.f, 0.f, 0.f);
        __stcs(&fo[col], z);
        __stcs(&fo[col + 64], z);
    } else {
        float4 a = fi[col];
        float4 b = fi[col + 64];
        __stcs(&fo[col],      make_float4(a.x * wv, a.y * wv, a.z * wv, a.w * wv));
        __stcs(&fo[col + 64], make_float4(b.x * wv, b.y * wv, b.z * wv, b.w * wv));
    }
}

// ---------------------------------------------------------------------------
extern "C" void kernel_launch(void* const* d_in, const int* in_sizes, int n_in,
                              void* d_out, int out_size) {
    const float* feat   = (const float*)d_in[0];
    const void*  src    = d_in[1];
    const void*  dst    = d_in[2];
    const float* weight = (const float*)d_in[3];
    const float* bias   = (const float*)d_in[4];
    long long E = (long long)in_sizes[1];
    long long EPG = E / BGRAPHS;
    int EPP = (int)((EPG + PPARTS - 1) / PPARTS);
    int use16 = (E <= (long long)ECAP) ? 1 : 0;

    k_deg_part<<<BGRAPHS * PPARTS, 256>>>(dst, EPG, EPP, use16, E);

    k_h<<<NTOT / 16, 256>>>(feat, weight);   // 8 warps/CTA, 2 rows/warp, +norm

    k_agg_part<<<BGRAPHS * PPARTS, 256>>>(src, dst, EPG, EPP, use16, E);

    k_rank<<<BGRAPHS, NPG>>>(bias);

    k_gate<<<NTOT / 4, 256>>>(feat, (float*)d_out);
}

// round 14
// speedup vs baseline: 1.0182x; 1.0182x over previous
#include <cuda_runtime.h>

#define BGRAPHS 64
#define NPG     1024
#define NTOT    (BGRAPHS * NPG)   // 65536
#define DIM     512
#define DROPN   512               // NPG - ceil(0.5*NPG)
#define PPARTS  16                // partial copies per graph (privatized reduce)
#define ECAP    (64 * 1024 * 32)  // dst16 cache capacity (expected E)

// ---- scratch (device globals: no allocation allowed) ----
__device__ float g_h[NTOT];
__device__ float g_norm[NTOT];
__device__ float g_w[NTOT];
__device__ float g_wb[NTOT];
__device__ int   g_pdeg[PPARTS * NTOT];          // 4 MB partial degree hist
__device__ float g_pagg[PPARTS * NTOT];          // 4 MB partial agg sums
__device__ unsigned short g_dst16[ECAP];         // 4 MB compacted local dst

// ---------------------------------------------------------------------------
// Warp-parallel int64-vs-int32 probe (warp 0 of a CTA): node indices < 2^17,
// so int64 data has all odd 32-bit words zero. 32 concurrent loads, one round
// trip, overlapped across CTAs.
// ---------------------------------------------------------------------------
__device__ __forceinline__ int warp_probe_is64(const void* p, long long nelem) {
    const unsigned* w = (const unsigned*)p;
    int lane = threadIdx.x & 31;
    int i = 1 + 2 * lane;
    unsigned v = ((long long)i < nelem * 2) ? w[i] : 0u;
    unsigned any = __ballot_sync(0xffffffffu, v != 0u);
    return any ? 0 : 1;
}

__device__ __forceinline__ int edge_idx(const void* p, long long e, int is64) {
    if (is64) return (int)((const long long*)p)[e];
    return ((const int*)p)[e];
}

// ---------------------------------------------------------------------------
// Degree partials: PPARTS CTAs per graph, shared int histogram, plain stores.
// Vectorized: 8 edges per thread per iteration. Compacts dst to uint16.
// ---------------------------------------------------------------------------
__global__ void k_deg_part(const void* __restrict__ dst, long long EPG,
                           int EPP, int use16, long long E) {
    __shared__ int sacc[NPG];
    __shared__ int s_is64;
    int g = blockIdx.x >> 4;
    int p = blockIdx.x & (PPARTS - 1);
    if (threadIdx.x < 32) {
        int r = warp_probe_is64(dst, E);
        if (threadIdx.x == 0) s_is64 = r;
    }
    for (int j = threadIdx.x; j < NPG; j += blockDim.x) sacc[j] = 0;
    __syncthreads();

    const int is64 = s_is64;
    long long base = (long long)g * EPG + (long long)p * EPP;
    long long rem = EPG - (long long)p * EPP;
    int cnt = (rem < (long long)EPP) ? (rem > 0 ? (int)rem : 0) : EPP;
    const int BS = 256;
    int t = threadIdx.x;
    int nfull = cnt >> 3;

    for (int gi = t; gi < nfull; gi += BS) {
        long long e0 = base + ((long long)gi << 3);
        int d[8];
        if (is64) {
            const longlong4* q = (const longlong4*)((const long long*)dst + e0);
            longlong4 a = q[0], b = q[1];
            d[0] = (int)a.x & (NPG - 1); d[1] = (int)a.y & (NPG - 1);
            d[2] = (int)a.z & (NPG - 1); d[3] = (int)a.w & (NPG - 1);
            d[4] = (int)b.x & (NPG - 1); d[5] = (int)b.y & (NPG - 1);
            d[6] = (int)b.z & (NPG - 1); d[7] = (int)b.w & (NPG - 1);
        } else {
            const int4* q = (const int4*)((const int*)dst + e0);
            int4 a = q[0], b = q[1];
            d[0] = a.x & (NPG - 1); d[1] = a.y & (NPG - 1);
            d[2] = a.z & (NPG - 1); d[3] = a.w & (NPG - 1);
            d[4] = b.x & (NPG - 1); d[5] = b.y & (NPG - 1);
            d[6] = b.z & (NPG - 1); d[7] = b.w & (NPG - 1);
        }
#pragma unroll
        for (int k = 0; k < 8; k++) atomicAdd(&sacc[d[k]], 1);
        if (use16) {
            uint4 s;
            s.x = (unsigned)d[0] | ((unsigned)d[1] << 16);
            s.y = (unsigned)d[2] | ((unsigned)d[3] << 16);
            s.z = (unsigned)d[4] | ((unsigned)d[5] << 16);
            s.w = (unsigned)d[6] | ((unsigned)d[7] << 16);
            *(uint4*)(g_dst16 + e0) = s;
        }
    }
    for (int e = (nfull << 3) + t; e < cnt; e += BS) {
        int d = edge_idx(dst, base + e, is64) & (NPG - 1);
        atomicAdd(&sacc[d], 1);
        if (use16) g_dst16[base + e] = (unsigned short)d;
    }
    __syncthreads();

    int out = p * NTOT + g * NPG;
    for (int j = threadIdx.x; j < NPG; j += blockDim.x)
        g_pdeg[out + j] = sacc[j];
}

// ---------------------------------------------------------------------------
// norm[i] = deg^-0.5 (0 if isolated); deg = sum of 16 partials, coalesced.
// ---------------------------------------------------------------------------
__global__ void k_norm() {
    int i = blockIdx.x * blockDim.x + threadIdx.x;
    if (i >= NTOT) return;
    int c = 0;
#pragma unroll
    for (int p = 0; p < PPARTS; p++) c += g_pdeg[p * NTOT + i];
    g_norm[i] = (c > 0) ? rsqrtf((float)c) : 0.0f;
}

// ---------------------------------------------------------------------------
// h[n] = dot(features[n,:], weight) * norm[n].  Two rows per warp, 256-thread
// CTAs; streaming loads — protects L2 for index/partial data.
// ---------------------------------------------------------------------------
__global__ void __launch_bounds__(256) k_h(const float* __restrict__ feat,
                                           const float* __restrict__ weight) {
    __shared__ float4 swt[DIM / 4];
    int t = threadIdx.x;
    if (t < DIM / 4) swt[t] = ((const float4*)weight)[t];
    __syncthreads();

    int warp = t >> 5, lane = t & 31;
    int row0 = (blockIdx.x * (blockDim.x >> 5) + warp) * 2;
    if (row0 >= NTOT) return;

    const float4* f0 = (const float4*)(feat + (long long)row0 * DIM);
    const float4* f1 = f0 + DIM / 4;
    float a0 = 0.f, a1 = 0.f;
#pragma unroll
    for (int k = 0; k < 4; k++) {
        float4 x = __ldcs(&f0[lane + 32 * k]);
        float4 y = __ldcs(&f1[lane + 32 * k]);
        float4 b = swt[lane + 32 * k];
        a0 += x.x * b.x + x.y * b.y + x.z * b.z + x.w * b.w;
        a1 += y.x * b.x + y.y * b.y + y.z * b.z + y.w * b.w;
    }
#pragma unroll
    for (int o = 16; o > 0; o >>= 1) {
        a0 += __shfl_down_sync(0xffffffffu, a0, o);
        a1 += __shfl_down_sync(0xffffffffu, a1, o);
    }
    if (lane == 0) {
        g_h[row0]     = a0 * g_norm[row0];
        g_h[row0 + 1] = a1 * g_norm[row0 + 1];
    }
}

// ---------------------------------------------------------------------------
// Agg partials: PPARTS CTAs per graph. h staged in shared, shared float
// accumulator, plain stores. Vectorized: 8 edges per thread per iteration.
// ---------------------------------------------------------------------------
__global__ void k_agg_part(const void* __restrict__ src,
                           const void* __restrict__ dst, long long EPG,
                           int EPP, int use16, long long E) {
    __shared__ float sh[NPG];
    __shared__ float sacc[NPG];
    __shared__ int s_is64;
    int g = blockIdx.x >> 4;
    int p = blockIdx.x & (PPARTS - 1);
    int hb = g * NPG;
    if (threadIdx.x < 32) {
        int r = warp_probe_is64(src, E);
        if (threadIdx.x == 0) s_is64 = r;
    }
    for (int j = threadIdx.x; j < NPG; j += blockDim.x) {
        sh[j] = g_h[hb + j];
        sacc[j] = 0.f;
    }
    __syncthreads();

    const int is64 = s_is64;
    long long base = (long long)g * EPG + (long long)p * EPP;
    long long rem = EPG - (long long)p * EPP;
    int cnt = (rem < (long long)EPP) ? (rem > 0 ? (int)rem : 0) : EPP;
    const int BS = 256;
    int t = threadIdx.x;
    int nfull = cnt >> 3;

    for (int gi = t; gi < nfull; gi += BS) {
        long long e0 = base + ((long long)gi << 3);
        int s[8], d[8];
        if (is64) {
            const longlong4* q = (const longlong4*)((const long long*)src + e0);
            longlong4 a = q[0], b = q[1];
            s[0] = (int)a.x & (NPG - 1); s[1] = (int)a.y & (NPG - 1);
            s[2] = (int)a.z & (NPG - 1); s[3] = (int)a.w & (NPG - 1);
            s[4] = (int)b.x & (NPG - 1); s[5] = (int)b.y & (NPG - 1);
            s[6] = (int)b.z & (NPG - 1); s[7] = (int)b.w & (NPG - 1);
        } else {
            const int4* q = (const int4*)((const int*)src + e0);
            int4 a = q[0], b = q[1];
            s[0] = a.x & (NPG - 1); s[1] = a.y & (NPG - 1);
            s[2] = a.z & (NPG - 1); s[3] = a.w & (NPG - 1);
            s[4] = b.x & (NPG - 1); s[5] = b.y & (NPG - 1);
            s[6] = b.z & (NPG - 1); s[7] = b.w & (NPG - 1);
        }
        if (use16) {
            uint4 q = *(const uint4*)(g_dst16 + e0);
            d[0] = (int)(q.x & 0xffffu); d[1] = (int)(q.x >> 16);
            d[2] = (int)(q.y & 0xffffu); d[3] = (int)(q.y >> 16);
            d[4] = (int)(q.z & 0xffffu); d[5] = (int)(q.z >> 16);
            d[6] = (int)(q.w & 0xffffu); d[7] = (int)(q.w >> 16);
        } else if (is64) {
            const longlong4* q = (const longlong4*)((const long long*)dst + e0);
            longlong4 a = q[0], b = q[1];
            d[0] = (int)a.x & (NPG - 1); d[1] = (int)a.y & (NPG - 1);
            d[2] = (int)a.z & (NPG - 1); d[3] = (int)a.w & (NPG - 1);
            d[4] = (int)b.x & (NPG - 1); d[5] = (int)b.y & (NPG - 1);
            d[6] = (int)b.z & (NPG - 1); d[7] = (int)b.w & (NPG - 1);
        } else {
            const int4* q = (const int4*)((const int*)dst + e0);
            int4 a = q[0], b = q[1];
            d[0] = a.x & (NPG - 1); d[1] = a.y & (NPG - 1);
            d[2] = a.z & (NPG - 1); d[3] = a.w & (NPG - 1);
            d[4] = b.x & (NPG - 1); d[5] = b.y & (NPG - 1);
            d[6] = b.z & (NPG - 1); d[7] = b.w & (NPG - 1);
        }
#pragma unroll
        for (int k = 0; k < 8; k++) atomicAdd(&sacc[d[k]], sh[s[k]]);
    }
    for (int e = (nfull << 3) + t; e < cnt; e += BS) {
        int si = edge_idx(src, base + e, is64) & (NPG - 1);
        int di = use16 ? (int)g_dst16[base + e]
                       : (edge_idx(dst, base + e, is64) & (NPG - 1));
        atomicAdd(&sacc[di], sh[si]);
    }
    __syncthreads();

    int out = p * NTOT + g * NPG;
    for (int j = threadIdx.x; j < NPG; j += blockDim.x)
        g_pagg[out + j] = sacc[j];
}

// ---------------------------------------------------------------------------
// w[i] = relu((sum of agg partials)*norm + bias).  Full-occupancy kernel:
// the 4 MB partial reduction runs at chip bandwidth here, NOT inside the
// 64-CTA rank kernel (which occupied <half the SMs).
// ---------------------------------------------------------------------------
__global__ void k_w(const float* __restrict__ bias) {
    int i = blockIdx.x * blockDim.x + threadIdx.x;
    if (i >= NTOT) return;
    float s = 0.f;
#pragma unroll
    for (int p = 0; p < PPARTS; p++) s += g_pagg[p * NTOT + i];
    float v = s * g_norm[i] + bias[0];
    g_w[i] = v > 0.f ? v : 0.f;
}

// ---------------------------------------------------------------------------
// Select-based top-k mask. One 1024-thread CTA per graph, reads only 256 KB.
//   T = key at stable-sort position DROPN-1 (4-pass MSD radix select)
//   keep iff key>T or (key==T and #{j<i: key_j==T} >= DROPN - #{key<T})
// Identical to rank_i = #{w_j<w_i}+#{j<i: w_j==w_i} >= DROPN.
// ---------------------------------------------------------------------------
__global__ void k_rank() {
    __shared__ int sbin[256];
    __shared__ int s_sel[2];
    __shared__ int s_wsum[32];
    __shared__ int s_nless;

    int g = blockIdx.x;
    int base = g * NPG;
    int i = threadIdx.x;
    int wid = i >> 5, lane = i & 31;

    float w = g_w[base + i];
    unsigned key = __float_as_uint(w);
    if (i == 0) { s_sel[0] = 0; s_sel[1] = DROPN - 1; s_nless = 0; }
    __syncthreads();

#pragma unroll
    for (int pass = 3; pass >= 0; pass--) {
        int shift = pass * 8;
        if (i < 256) sbin[i] = 0;
        __syncthreads();
        unsigned prefix = (unsigned)s_sel[0];
        bool match = (pass == 3) || ((key >> (shift + 8)) == prefix);
        if (match) atomicAdd(&sbin[(key >> shift) & 255], 1);
        __syncthreads();
        if (i < 32) {
            int r = s_sel[1];
            int loc[8], lsum = 0;
#pragma unroll
            for (int t = 0; t < 8; t++) { loc[t] = sbin[i * 8 + t]; lsum += loc[t]; }
            int incl = lsum;
#pragma unroll
            for (int o = 1; o < 32; o <<= 1) {
                int y = __shfl_up_sync(0xffffffffu, incl, o);
                if (lane >= o) incl += y;
            }
            int excl = incl - lsum;
            bool has = (excl <= r) && (r < incl);
            if (has) {
                int rr = r - excl;
                int b = 0;
#pragma unroll
                for (int t = 0; t < 8; t++) {
                    if (rr >= loc[t] && b == t) { rr -= loc[t]; b = t + 1; }
                }
                int binfull = i * 8 + b;
                s_sel[0] = (pass == 3) ? binfull : (int)((prefix << 8) | (unsigned)binfull);
                s_sel[1] = rr;
            }
        }
        __syncthreads();
    }

    unsigned T = (unsigned)s_sel[0];

    unsigned lm = __ballot_sync(0xffffffffu, key < T);
    unsigned em = __ballot_sync(0xffffffffu, key == T);
    if (lane == 0) {
        atomicAdd(&s_nless, __popc(lm));
        s_wsum[wid] = __popc(em);
    }
    __syncthreads();
    if (i < 32) {
        int x = s_wsum[i];
        int incl = x;
#pragma unroll
        for (int o = 1; o < 32; o <<= 1) {
            int y = __shfl_up_sync(0xffffffffu, incl, o);
            if (lane >= o) incl += y;
        }
        s_wsum[i] = incl - x;
    }
    __syncthreads();

    int pos = s_wsum[wid] + __popc(em & ((1u << lane) - 1u));
    int needEq = DROPN - s_nless;
    bool keep = (key > T) || ((key == T) && (pos >= needEq));
    g_wb[base + i] = keep ? w : 0.f;
}

// ---------------------------------------------------------------------------
// out[n,:] = features[n,:] * wb[n].  2 rows per 256-thread CTA (measured-good
// R10 form); zero rows skip the feature read; streaming loads and stores.
// ---------------------------------------------------------------------------
__global__ void __launch_bounds__(256) k_gate(const float* __restrict__ feat,
                                              float* __restrict__ out) {
    int row = blockIdx.x * 2 + (threadIdx.x >> 7);
    int col = threadIdx.x & 127;
    float wv = g_wb[row];
    const float4* fi = (const float4*)(feat + (long long)row * DIM);
    float4* fo = (float4*)(out + (long long)row * DIM);
    float4 r;
    if (wv == 0.f) {
        r = make_float4(0.f, 0.f, 0.f, 0.f);
    } else {
        float4 a = __ldcs(&fi[col]);
        r = make_float4(a.x * wv, a.y * wv, a.z * wv, a.w * wv);
    }
    __stcs(&fo[col], r);
}

// ---------------------------------------------------------------------------
extern "C" void kernel_launch(void* const* d_in, const int* in_sizes, int n_in,
                              void* d_out, int out_size) {
    const float* feat   = (const float*)d_in[0];
    const void*  src    = d_in[1];
    const void*  dst    = d_in[2];
    const float* weight = (const float*)d_in[3];
    const float* bias   = (const float*)d_in[4];
    long long E = (long long)in_sizes[1];
    long long EPG = E / BGRAPHS;
    int EPP = (int)((EPG + PPARTS - 1) / PPARTS);
    int use16 = (E <= (long long)ECAP) ? 1 : 0;

    k_deg_part<<<BGRAPHS * PPARTS, 256>>>(dst, EPG, EPP, use16, E);
    k_norm<<<NTOT / 256, 256>>>();

    k_h<<<NTOT / 16, 256>>>(feat, weight);   // 8 warps/CTA, 2 rows/warp

    k_agg_part<<<BGRAPHS * PPARTS, 256>>>(src, dst, EPG, EPP, use16, E);

    k_w<<<NTOT / 256, 256>>>(bias);
    k_rank<<<BGRAPHS, NPG>>>();

    k_gate<<<NTOT / 2, 256>>>(feat, (float*)d_out);
}

// round 16
// speedup vs baseline: 1.0367x; 1.0182x over previous
#include <cuda_runtime.h>

#define BGRAPHS 64
#define NPG     1024
#define NTOT    (BGRAPHS * NPG)   // 65536
#define DIM     512
#define DROPN   512               // NPG - ceil(0.5*NPG)
#define PPARTS  16                // partial copies per graph (privatized reduce)
#define ECAP    (64 * 1024 * 32)  // dst16 cache capacity (expected E)
#define DEG_CTAS (BGRAPHS * PPARTS)        // 1024 deg-role CTAs
#define H_CTAS   (NTOT / 16)               // 4096 hraw-role CTAs (2 rows/warp, 8 warps)

// ---- scratch (device globals: no allocation allowed) ----
__device__ float g_h[NTOT];               // RAW dot products (no norm)
__device__ float g_norm[NTOT];
__device__ float g_w[NTOT];
__device__ float g_wb[NTOT];
__device__ int   g_pdeg[PPARTS * NTOT];          // 4 MB partial degree hist
__device__ float g_pagg[PPARTS * NTOT];          // 4 MB partial agg sums
__device__ unsigned short g_dst16[ECAP];         // 4 MB compacted local dst

// ---------------------------------------------------------------------------
// Warp-parallel int64-vs-int32 probe: node indices < 2^17, so int64 data has
// all odd 32-bit words zero. 32 concurrent loads, one round trip.
// ---------------------------------------------------------------------------
__device__ __forceinline__ int warp_probe_is64(const void* p, long long nelem) {
    const unsigned* w = (const unsigned*)p;
    int lane = threadIdx.x & 31;
    int i = 1 + 2 * lane;
    unsigned v = ((long long)i < nelem * 2) ? w[i] : 0u;
    unsigned any = __ballot_sync(0xffffffffu, v != 0u);
    return any ? 0 : 1;
}

__device__ __forceinline__ int edge_idx(const void* p, long long e, int is64) {
    if (is64) return (int)((const long long*)p)[e];
    return ((const int*)p)[e];
}

// ---------------------------------------------------------------------------
// K1: heterogeneous kernel.
//   Blocks [0, DEG_CTAS):       degree partials (shared histogram, atomic-
//                               bound) + dst16 compaction.
//   Blocks [DEG_CTAS, +H_CTAS): hraw[n] = dot(features[n,:], weight) — RAW,
//                               no norm (deferred to agg staging). DRAM-bound.
// The two roles use disjoint pipes (ATOMS/L1 vs DRAM) and overlap on-chip.
// ---------------------------------------------------------------------------
__global__ void __launch_bounds__(256) k_deg_h(
        const void* __restrict__ dst, long long EPG, int EPP, int use16,
        long long E, const float* __restrict__ feat,
        const float* __restrict__ weight) {
    __shared__ int smem_buf[NPG];          // deg: histogram; h: weight cache

    if (blockIdx.x < DEG_CTAS) {
        // ------------------------- degree role -------------------------
        __shared__ int s_is64;
        int* sacc = smem_buf;
        int g = blockIdx.x >> 4;
        int p = blockIdx.x & (PPARTS - 1);
        if (threadIdx.x < 32) {
            int r = warp_probe_is64(dst, E);
            if (threadIdx.x == 0) s_is64 = r;
        }
        for (int j = threadIdx.x; j < NPG; j += blockDim.x) sacc[j] = 0;
        __syncthreads();

        const int is64 = s_is64;
        long long base = (long long)g * EPG + (long long)p * EPP;
        long long rem = EPG - (long long)p * EPP;
        int cnt = (rem < (long long)EPP) ? (rem > 0 ? (int)rem : 0) : EPP;
        const int BS = 256;
        int t = threadIdx.x;
        int nfull = cnt >> 3;

        for (int gi = t; gi < nfull; gi += BS) {
            long long e0 = base + ((long long)gi << 3);
            int d[8];
            if (is64) {
                const longlong4* q = (const longlong4*)((const long long*)dst + e0);
                longlong4 a = q[0], b = q[1];
                d[0] = (int)a.x & (NPG - 1); d[1] = (int)a.y & (NPG - 1);
                d[2] = (int)a.z & (NPG - 1); d[3] = (int)a.w & (NPG - 1);
                d[4] = (int)b.x & (NPG - 1); d[5] = (int)b.y & (NPG - 1);
                d[6] = (int)b.z & (NPG - 1); d[7] = (int)b.w & (NPG - 1);
            } else {
                const int4* q = (const int4*)((const int*)dst + e0);
                int4 a = q[0], b = q[1];
                d[0] = a.x & (NPG - 1); d[1] = a.y & (NPG - 1);
                d[2] = a.z & (NPG - 1); d[3] = a.w & (NPG - 1);
                d[4] = b.x & (NPG - 1); d[5] = b.y & (NPG - 1);
                d[6] = b.z & (NPG - 1); d[7] = b.w & (NPG - 1);
            }
#pragma unroll
            for (int k = 0; k < 8; k++) atomicAdd(&sacc[d[k]], 1);
            if (use16) {
                uint4 s;
                s.x = (unsigned)d[0] | ((unsigned)d[1] << 16);
                s.y = (unsigned)d[2] | ((unsigned)d[3] << 16);
                s.z = (unsigned)d[4] | ((unsigned)d[5] << 16);
                s.w = (unsigned)d[6] | ((unsigned)d[7] << 16);
                *(uint4*)(g_dst16 + e0) = s;
            }
        }
        for (int e = (nfull << 3) + t; e < cnt; e += BS) {
            int d = edge_idx(dst, base + e, is64) & (NPG - 1);
            atomicAdd(&sacc[d], 1);
            if (use16) g_dst16[base + e] = (unsigned short)d;
        }
        __syncthreads();

        int out = p * NTOT + g * NPG;
        for (int j = threadIdx.x; j < NPG; j += blockDim.x)
            g_pdeg[out + j] = sacc[j];
    } else {
        // --------------------------- hraw role --------------------------
        float4* swt = (float4*)smem_buf;   // 128 float4 = 2 KB
        int t = threadIdx.x;
        if (t < DIM / 4) swt[t] = ((const float4*)weight)[t];
        __syncthreads();

        int bid = blockIdx.x - DEG_CTAS;
        int warp = t >> 5, lane = t & 31;
        int row0 = (bid * 8 + warp) * 2;   // 8 warps/CTA, 2 rows/warp
        if (row0 >= NTOT) return;

        const float4* f0 = (const float4*)(feat + (long long)row0 * DIM);
        const float4* f1 = f0 + DIM / 4;
        float a0 = 0.f, a1 = 0.f;
#pragma unroll
        for (int k = 0; k < 4; k++) {
            float4 x = __ldcs(&f0[lane + 32 * k]);
            float4 y = __ldcs(&f1[lane + 32 * k]);
            float4 b = swt[lane + 32 * k];
            a0 += x.x * b.x + x.y * b.y + x.z * b.z + x.w * b.w;
            a1 += y.x * b.x + y.y * b.y + y.z * b.z + y.w * b.w;
        }
#pragma unroll
        for (int o = 16; o > 0; o >>= 1) {
            a0 += __shfl_down_sync(0xffffffffu, a0, o);
            a1 += __shfl_down_sync(0xffffffffu, a1, o);
        }
        if (lane == 0) {
            g_h[row0]     = a0;            // raw — norm applied at agg staging
            g_h[row0 + 1] = a1;
        }
    }
}

// ---------------------------------------------------------------------------
// norm[i] = deg^-0.5 (0 if isolated); deg = sum of 16 partials, coalesced.
// ---------------------------------------------------------------------------
__global__ void k_norm() {
    int i = blockIdx.x * blockDim.x + threadIdx.x;
    if (i >= NTOT) return;
    int c = 0;
#pragma unroll
    for (int p = 0; p < PPARTS; p++) c += g_pdeg[p * NTOT + i];
    g_norm[i] = (c > 0) ? rsqrtf((float)c) : 0.0f;
}

// ---------------------------------------------------------------------------
// Agg partials: PPARTS CTAs per graph. Stages h = hraw*norm in shared,
// shared float accumulator, plain stores. 8 edges/thread/iteration.
// ---------------------------------------------------------------------------
__global__ void k_agg_part(const void* __restrict__ src,
                           const void* __restrict__ dst, long long EPG,
                           int EPP, int use16, long long E) {
    __shared__ float sh[NPG];
    __shared__ float sacc[NPG];
    __shared__ int s_is64;
    int g = blockIdx.x >> 4;
    int p = blockIdx.x & (PPARTS - 1);
    int hb = g * NPG;
    if (threadIdx.x < 32) {
        int r = warp_probe_is64(src, E);
        if (threadIdx.x == 0) s_is64 = r;
    }
    for (int j = threadIdx.x; j < NPG; j += blockDim.x) {
        sh[j] = g_h[hb + j] * g_norm[hb + j];    // norm applied here
        sacc[j] = 0.f;
    }
    __syncthreads();

    const int is64 = s_is64;
    long long base = (long long)g * EPG + (long long)p * EPP;
    long long rem = EPG - (long long)p * EPP;
    int cnt = (rem < (long long)EPP) ? (rem > 0 ? (int)rem : 0) : EPP;
    const int BS = 256;
    int t = threadIdx.x;
    int nfull = cnt >> 3;

    for (int gi = t; gi < nfull; gi += BS) {
        long long e0 = base + ((long long)gi << 3);
        int s[8], d[8];
        if (is64) {
            const longlong4* q = (const longlong4*)((const long long*)src + e0);
            longlong4 a = q[0], b = q[1];
            s[0] = (int)a.x & (NPG - 1); s[1] = (int)a.y & (NPG - 1);
            s[2] = (int)a.z & (NPG - 1); s[3] = (int)a.w & (NPG - 1);
            s[4] = (int)b.x & (NPG - 1); s[5] = (int)b.y & (NPG - 1);
            s[6] = (int)b.z & (NPG - 1); s[7] = (int)b.w & (NPG - 1);
        } else {
            const int4* q = (const int4*)((const int*)src + e0);
            int4 a = q[0], b = q[1];
            s[0] = a.x & (NPG - 1); s[1] = a.y & (NPG - 1);
            s[2] = a.z & (NPG - 1); s[3] = a.w & (NPG - 1);
            s[4] = b.x & (NPG - 1); s[5] = b.y & (NPG - 1);
            s[6] = b.z & (NPG - 1); s[7] = b.w & (NPG - 1);
        }
        if (use16) {
            uint4 q = *(const uint4*)(g_dst16 + e0);
            d[0] = (int)(q.x & 0xffffu); d[1] = (int)(q.x >> 16);
            d[2] = (int)(q.y & 0xffffu); d[3] = (int)(q.y >> 16);
            d[4] = (int)(q.z & 0xffffu); d[5] = (int)(q.z >> 16);
            d[6] = (int)(q.w & 0xffffu); d[7] = (int)(q.w >> 16);
        } else if (is64) {
            const longlong4* q = (const longlong4*)((const long long*)dst + e0);
            longlong4 a = q[0], b = q[1];
            d[0] = (int)a.x & (NPG - 1); d[1] = (int)a.y & (NPG - 1);
            d[2] = (int)a.z & (NPG - 1); d[3] = (int)a.w & (NPG - 1);
            d[4] = (int)b.x & (NPG - 1); d[5] = (int)b.y & (NPG - 1);
            d[6] = (int)b.z & (NPG - 1); d[7] = (int)b.w & (NPG - 1);
        } else {
            const int4* q = (const int4*)((const int*)dst + e0);
            int4 a = q[0], b = q[1];
            d[0] = a.x & (NPG - 1); d[1] = a.y & (NPG - 1);
            d[2] = a.z & (NPG - 1); d[3] = a.w & (NPG - 1);
            d[4] = b.x & (NPG - 1); d[5] = b.y & (NPG - 1);
            d[6] = b.z & (NPG - 1); d[7] = b.w & (NPG - 1);
        }
#pragma unroll
        for (int k = 0; k < 8; k++) atomicAdd(&sacc[d[k]], sh[s[k]]);
    }
    for (int e = (nfull << 3) + t; e < cnt; e += BS) {
        int si = edge_idx(src, base + e, is64) & (NPG - 1);
        int di = use16 ? (int)g_dst16[base + e]
                       : (edge_idx(dst, base + e, is64) & (NPG - 1));
        atomicAdd(&sacc[di], sh[si]);
    }
    __syncthreads();

    int out = p * NTOT + g * NPG;
    for (int j = threadIdx.x; j < NPG; j += blockDim.x)
        g_pagg[out + j] = sacc[j];
}

// ---------------------------------------------------------------------------
// w[i] = relu((sum of agg partials)*norm + bias).  Full-occupancy reduction.
// ---------------------------------------------------------------------------
__global__ void k_w(const float* __restrict__ bias) {
    int i = blockIdx.x * blockDim.x + threadIdx.x;
    if (i >= NTOT) return;
    float s = 0.f;
#pragma unroll
    for (int p = 0; p < PPARTS; p++) s += g_pagg[p * NTOT + i];
    float v = s * g_norm[i] + bias[0];
    g_w[i] = v > 0.f ? v : 0.f;
}

// ---------------------------------------------------------------------------
// Select-based top-k mask. One 1024-thread CTA per graph, reads 256 KB.
//   T = key at stable-sort position DROPN-1 (4-pass MSD radix select)
//   keep iff key>T or (key==T and #{j<i: key_j==T} >= DROPN - #{key<T})
// Identical to rank_i = #{w_j<w_i}+#{j<i: w_j==w_i} >= DROPN.
// ---------------------------------------------------------------------------
__global__ void k_rank() {
    __shared__ int sbin[256];
    __shared__ int s_sel[2];
    __shared__ int s_wsum[32];
    __shared__ int s_nless;

    int g = blockIdx.x;
    int base = g * NPG;
    int i = threadIdx.x;
    int wid = i >> 5, lane = i & 31;

    float w = g_w[base + i];
    unsigned key = __float_as_uint(w);
    if (i == 0) { s_sel[0] = 0; s_sel[1] = DROPN - 1; s_nless = 0; }
    __syncthreads();

#pragma unroll
    for (int pass = 3; pass >= 0; pass--) {
        int shift = pass * 8;
        if (i < 256) sbin[i] = 0;
        __syncthreads();
        unsigned prefix = (unsigned)s_sel[0];
        bool match = (pass == 3) || ((key >> (shift + 8)) == prefix);
        if (match) atomicAdd(&sbin[(key >> shift) & 255], 1);
        __syncthreads();
        if (i < 32) {
            int r = s_sel[1];
            int loc[8], lsum = 0;
#pragma unroll
            for (int t = 0; t < 8; t++) { loc[t] = sbin[i * 8 + t]; lsum += loc[t]; }
            int incl = lsum;
#pragma unroll
            for (int o = 1; o < 32; o <<= 1) {
                int y = __shfl_up_sync(0xffffffffu, incl, o);
                if (lane >= o) incl += y;
            }
            int excl = incl - lsum;
            bool has = (excl <= r) && (r < incl);
            if (has) {
                int rr = r - excl;
                int b = 0;
#pragma unroll
                for (int t = 0; t < 8; t++) {
                    if (rr >= loc[t] && b == t) { rr -= loc[t]; b = t + 1; }
                }
                int binfull = i * 8 + b;
                s_sel[0] = (pass == 3) ? binfull : (int)((prefix << 8) | (unsigned)binfull);
                s_sel[1] = rr;
            }
        }
        __syncthreads();
    }

    unsigned T = (unsigned)s_sel[0];

    unsigned lm = __ballot_sync(0xffffffffu, key < T);
    unsigned em = __ballot_sync(0xffffffffu, key == T);
    if (lane == 0) {
        atomicAdd(&s_nless, __popc(lm));
        s_wsum[wid] = __popc(em);
    }
    __syncthreads();
    if (i < 32) {
        int x = s_wsum[i];
        int incl = x;
#pragma unroll
        for (int o = 1; o < 32; o <<= 1) {
            int y = __shfl_up_sync(0xffffffffu, incl, o);
            if (lane >= o) incl += y;
        }
        s_wsum[i] = incl - x;
    }
    __syncthreads();

    int pos = s_wsum[wid] + __popc(em & ((1u << lane) - 1u));
    int needEq = DROPN - s_nless;
    bool keep = (key > T) || ((key == T) && (pos >= needEq));
    g_wb[base + i] = keep ? w : 0.f;
}

// ---------------------------------------------------------------------------
// out[n,:] = features[n,:] * wb[n].  2 rows per 256-thread CTA; zero rows
// skip the feature read; streaming loads and stores.
// ---------------------------------------------------------------------------
__global__ void __launch_bounds__(256) k_gate(const float* __restrict__ feat,
                                              float* __restrict__ out) {
    int row = blockIdx.x * 2 + (threadIdx.x >> 7);
    int col = threadIdx.x & 127;
    float wv = g_wb[row];
    const float4* fi = (const float4*)(feat + (long long)row * DIM);
    float4* fo = (float4*)(out + (long long)row * DIM);
    float4 r;
    if (wv == 0.f) {
        r = make_float4(0.f, 0.f, 0.f, 0.f);
    } else {
        float4 a = __ldcs(&fi[col]);
        r = make_float4(a.x * wv, a.y * wv, a.z * wv, a.w * wv);
    }
    __stcs(&fo[col], r);
}

// ---------------------------------------------------------------------------
extern "C" void kernel_launch(void* const* d_in, const int* in_sizes, int n_in,
                              void* d_out, int out_size) {
    const float* feat   = (const float*)d_in[0];
    const void*  src    = d_in[1];
    const void*  dst    = d_in[2];
    const float* weight = (const float*)d_in[3];
    const float* bias   = (const float*)d_in[4];
    long long E = (long long)in_sizes[1];
    long long EPG = E / BGRAPHS;
    int EPP = (int)((EPG + PPARTS - 1) / PPARTS);
    int use16 = (E <= (long long)ECAP) ? 1 : 0;

    // K1: deg partials (CTAs 0..1023) overlapped with raw matvec (1024..5119)
    k_deg_h<<<DEG_CTAS + H_CTAS, 256>>>(dst, EPG, EPP, use16, E, feat, weight);

    k_norm<<<NTOT / 256, 256>>>();

    k_agg_part<<<BGRAPHS * PPARTS, 256>>>(src, dst, EPG, EPP, use16, E);

    k_w<<<NTOT / 256, 256>>>(bias);
    k_rank<<<BGRAPHS, NPG>>>();

    k_gate<<<NTOT / 2, 256>>>(feat, (float*)d_out);
}